// round 14
// baseline (speedup 1.0000x reference)
#include <cuda_runtime.h>
#include <cuda_bf16.h>
#include <math.h>
#include <stdint.h>

#define NTOK 8192
#define DIM  1024
#define FFN  4096
#define NE   10

typedef __nv_bfloat16 bf16;

// ---------------- scratch (device globals: no allocation allowed) ----------
__device__ bf16  g_Ab [(size_t)NTOK * FFN];   // shared gelu acts (token rows)
__device__ bf16  g_Ad [(size_t)NTOK * FFN];   // domain gelu acts (perm rows)
__device__ float g_G  [(size_t)NTOK * DIM];   // shared gate values (token rows)
__device__ float g_Gd [(size_t)NTOK * DIM];   // domain gate values (perm rows)
__device__ float g_Xg [(size_t)NTOK * DIM];   // gathered x fp32 (perm rows)
__device__ bf16  g_Xb [(size_t)NTOK * DIM];   // x bf16 (token rows)
__device__ bf16  g_Xgb[(size_t)NTOK * DIM];   // gathered x bf16 (perm rows)
__device__ int   g_perm[NTOK];
__device__ int   g_cnt[NE];
__device__ int   g_off[NE];
__device__ int   g_cur[NE];
__device__ int   g_tileTab[80];
__device__ int   g_ntile;
__device__ int   g_task;                      // persistent task counter
__device__ int   g_rowCnt[160];               // per-row-group producer counters
__device__ int   g_colCnt[8];                 // shared-MIX per-column counters

// transposed bf16 weights: Wt[n*K + k] = bf16(W[k*N + n])
__device__ bf16 g_sW1t[(size_t)FFN * DIM];
__device__ bf16 g_sW2t[(size_t)DIM * FFN];
__device__ bf16 g_sWgt[(size_t)DIM * DIM];
__device__ bf16 g_dW1t[(size_t)NE * FFN * DIM];
__device__ bf16 g_dW2t[(size_t)NE * DIM * FFN];
__device__ bf16 g_dWgt[(size_t)NE * DIM * DIM];

// gemm task layout: rows 0..137 (64 shared + 74 domain slots)
//   t in [0, 5520): r=t/40, c=t%40; c<32 -> ACT (r,c); else GATE (r,c-32)
//   t in [5520, 6032): MIX shared (gy=u>>3, bx=u&7)
//   t in [6032, 6624): MIX domain (gy=64+(v>>3), bx=v&7)
#define NROW       138
#define TASK_PROD  (NROW * 40)
#define MIX_SH     512
#define TASK_TOTAL (TASK_PROD + MIX_SH + 592)
#define DEP_TARGET 40

// ---------------- PTX helpers ------------------------------------------------
__device__ __forceinline__ uint32_t smem_u32(const void* p) {
    uint32_t a;
    asm("{ .reg .u64 t; cvta.to.shared.u64 t, %1; cvt.u32.u64 %0, t; }" : "=r"(a) : "l"(p));
    return a;
}
__device__ __forceinline__ void cp16(uint32_t dst, const void* src, int srcbytes) {
    asm volatile("cp.async.cg.shared.global [%0], [%1], 16, %2;"
                 :: "r"(dst), "l"(src), "r"(srcbytes) : "memory");
}
__device__ __forceinline__ void cp_commit() {
    asm volatile("cp.async.commit_group;" ::: "memory");
}
template <int N>
__device__ __forceinline__ void cp_wait() {
    asm volatile("cp.async.wait_group %0;" :: "n"(N) : "memory");
}
__device__ __forceinline__ void ldsm_x4(uint32_t* r, uint32_t addr) {
    asm volatile("ldmatrix.sync.aligned.m8n8.x4.shared.b16 {%0,%1,%2,%3}, [%4];"
                 : "=r"(r[0]), "=r"(r[1]), "=r"(r[2]), "=r"(r[3]) : "r"(addr));
}
__device__ __forceinline__ void ldsm_x2(uint32_t* r, uint32_t addr) {
    asm volatile("ldmatrix.sync.aligned.m8n8.x2.shared.b16 {%0,%1}, [%2];"
                 : "=r"(r[0]), "=r"(r[1]) : "r"(addr));
}
__device__ __forceinline__ void mma_bf16(float* c, const uint32_t* a, const uint32_t* b) {
    asm volatile(
        "mma.sync.aligned.m16n8k16.row.col.f32.bf16.bf16.f32 "
        "{%0,%1,%2,%3},{%4,%5,%6,%7},{%8,%9},{%0,%1,%2,%3};"
        : "+f"(c[0]), "+f"(c[1]), "+f"(c[2]), "+f"(c[3])
        : "r"(a[0]), "r"(a[1]), "r"(a[2]), "r"(a[3]), "r"(b[0]), "r"(b[1]));
}
__device__ __forceinline__ void spin_ge(volatile int* p, int tgt) {
    while (*p < tgt) __nanosleep(64);
}

// ---------------- routing + converts -----------------------------------------
__global__ void k_zero() {
    int i = threadIdx.x;
    if (i < NE)  { g_cnt[i] = 0; g_cur[i] = 0; }
    if (i < 160) g_rowCnt[i] = 0;
    if (i < 8)   g_colCnt[i] = 0;
    if (i == 255) g_task = 0;
}
__global__ void k_count_cvt(const int* __restrict__ ids, const float* __restrict__ x) {
    int i = blockIdx.x * blockDim.x + threadIdx.x;
    float4 v = ((const float4*)x)[i];
    union { __nv_bfloat162 h; uint32_t u; } a, b;
    a.h = __floats2bfloat162_rn(v.x, v.y);
    b.h = __floats2bfloat162_rn(v.z, v.w);
    ((uint2*)g_Xb)[i] = make_uint2(a.u, b.u);
    if (i < NTOK) atomicAdd(&g_cnt[ids[i]], 1);
}
__global__ void k_scan() {
    if (threadIdx.x == 0) {
        int s = 0;
        for (int e = 0; e < NE; e++) { g_off[e] = s; s += g_cnt[e]; }
        int t = 0;
        for (int e = 0; e < NE; e++) {
            int nt = (g_cnt[e] + 127) >> 7;
            for (int q = 0; q < nt; q++) g_tileTab[t++] = (e << 16) | q;
        }
        g_ntile = t;
    }
}
__global__ void k_scatter(const int* __restrict__ ids) {
    int i = blockIdx.x * blockDim.x + threadIdx.x;
    if (i < NTOK) {
        int e = ids[i];
        int p = g_off[e] + atomicAdd(&g_cur[e], 1);
        g_perm[p] = i;
    }
}
__global__ void k_gather(const float* __restrict__ x) {
    int p   = blockIdx.x;
    int src = g_perm[p];
    float4 v = ((const float4*)(x + (size_t)src * DIM))[threadIdx.x];
    ((float4*)(g_Xg + (size_t)p * DIM))[threadIdx.x] = v;
    union { __nv_bfloat162 h; uint32_t u; } a, b;
    a.h = __floats2bfloat162_rn(v.x, v.y);
    b.h = __floats2bfloat162_rn(v.z, v.w);
    ((uint2*)(g_Xgb + (size_t)p * DIM))[threadIdx.x] = make_uint2(a.u, b.u);
}

// ---------------- single merged transpose+convert launch ---------------------
__global__ void k_transpose_all(
    const float* __restrict__ sW1, const float* __restrict__ sW2,
    const float* __restrict__ sWg, const float* __restrict__ dW1,
    const float* __restrict__ dW2, const float* __restrict__ dWg)
{
    int b = blockIdx.x;
    const float* W; bf16* Wt; int K, N;
    if (b < 4096)                { W = sW1; Wt = g_sW1t; K = DIM; N = FFN; }
    else if ((b -= 4096) < 4096) { W = sW2; Wt = g_sW2t; K = FFN; N = DIM; }
    else if ((b -= 4096) < 1024) { W = sWg; Wt = g_sWgt; K = DIM; N = DIM; }
    else if ((b -= 1024) < 40960) {
        int e = b / 4096; b -= e * 4096;
        W = dW1 + (size_t)e * DIM * FFN; Wt = g_dW1t + (size_t)e * DIM * FFN;
        K = DIM; N = FFN;
    }
    else if ((b -= 40960) < 40960) {
        int e = b / 4096; b -= e * 4096;
        W = dW2 + (size_t)e * DIM * FFN; Wt = g_dW2t + (size_t)e * DIM * FFN;
        K = FFN; N = DIM;
    }
    else {
        b -= 40960;
        int e = b / 1024; b -= e * 1024;
        W = dWg + (size_t)e * DIM * DIM; Wt = g_dWgt + (size_t)e * DIM * DIM;
        K = DIM; N = DIM;
    }
    int nb = N >> 5;
    int n0 = (b % nb) * 32, k0 = (b / nb) * 32;

    __shared__ float t[32][33];
#pragma unroll
    for (int i = threadIdx.y; i < 32; i += 8)
        t[i][threadIdx.x] = W[(size_t)(k0 + i) * N + n0 + threadIdx.x];
    __syncthreads();
#pragma unroll
    for (int i = threadIdx.y; i < 32; i += 8)
        Wt[(size_t)(n0 + i) * K + k0 + threadIdx.x] = __float2bfloat16(t[threadIdx.x][i]);
}

// ---------------- persistent fused GEMM --------------------------------------
#define ROWB   144
#define BUFBY  (128 * ROWB)
#define STAGES 3
#define SMEM_BYTES (STAGES * 2 * BUFBY)

#define TASK_ACT  0
#define TASK_GATE 1
#define TASK_MIX  2

__device__ __forceinline__ bool dom_tile(int idx, int& e, int& Mloc,
                                         int& rowBase, int& rowTile) {
    if (idx >= g_ntile) return false;
    int pk  = g_tileTab[idx];
    e       = pk >> 16;
    rowTile = (pk & 0xffff) * 128;
    Mloc    = g_cnt[e];
    rowBase = g_off[e];
    return true;
}

__global__ void __launch_bounds__(256, 2) gemm_persist(
    const float* __restrict__ xf,
    const float* __restrict__ sb1, const float* __restrict__ db1,
    const float* __restrict__ sbg, const float* __restrict__ dbg,
    const float* __restrict__ sb2, const float* __restrict__ db2,
    float* __restrict__ out)
{
    extern __shared__ uint8_t sm[];
    __shared__ int s_task;
    uint32_t asb = smem_u32(sm);
    uint32_t bsb = asb + STAGES * BUFBY;

    int tid   = threadIdx.x;
    int lane  = tid & 31;
    int warp  = tid >> 5;
    int warpM = warp >> 2;
    int warpN = warp & 3;

    int srow = tid >> 3;
    int sseg = (tid & 7) * 8;
    int aoffB = (lane & 15) * ROWB + ((lane >> 4) << 4);
    int boffB = (lane & 7)  * ROWB + (((lane >> 3) & 1) << 4);
    int grp = lane >> 2, t4 = lane & 3;

    for (;;) {
        if (tid == 0) s_task = atomicAdd(&g_task, 1);
        __syncthreads();                  // all warps done with prior tile's smem
        int t = s_task;
        if (t >= TASK_TOTAL) return;

        // ---- decode ----
        int task, gy, bx;
        if (t < TASK_PROD) {
            gy = t / 40; int c = t - gy * 40;
            if (c < 32) { task = TASK_ACT;  bx = c; }
            else        { task = TASK_GATE; bx = c - 32; }
        } else if (t < TASK_PROD + MIX_SH) {
            int u = t - TASK_PROD;
            task = TASK_MIX; gy = u >> 3; bx = u & 7;
        } else {
            int u = t - TASK_PROD - MIX_SH;
            task = TASK_MIX; gy = 64 + (u >> 3); bx = u & 7;
        }

        bool dom = gy >= 64;
        int e = 0, Mloc = NTOK, rowBase = 0, rowTile = 0;
        if (!dom) rowTile = gy * 128;
        else if (!dom_tile(gy - 64, e, Mloc, rowBase, rowTile)) continue;

        const bf16 *A, *Wt;
        const float* bias;
        int K;
        if (task == TASK_ACT) {
            K = DIM;
            A    = dom ? g_Xgb + (size_t)rowBase * K : g_Xb;
            Wt   = dom ? g_dW1t + (size_t)e * (size_t)K * FFN : g_sW1t;
            bias = dom ? db1 + (size_t)e * FFN : sb1;
        } else if (task == TASK_GATE) {
            K = DIM;
            A    = dom ? g_Xgb + (size_t)rowBase * K : g_Xb;
            Wt   = dom ? g_dWgt + (size_t)e * (size_t)K * DIM : g_sWgt;
            bias = dom ? dbg + (size_t)e * DIM : sbg;
        } else {
            K = FFN;
            A    = (dom ? g_Ad : g_Ab) + (dom ? (size_t)rowBase * K : 0);
            Wt   = dom ? g_dW2t + (size_t)e * (size_t)K * DIM : g_sW2t;
            bias = dom ? db2 + (size_t)e * DIM : sb2;
            // wait for this row-group's 32 act + 8 gate producers
            if (tid == 0) spin_ge(&g_rowCnt[gy], DEP_TARGET);
            __syncthreads();
            __threadfence();              // acquire
        }

        int colTile = bx * 128;

        float acc[4][4][4];
#pragma unroll
        for (int mi = 0; mi < 4; mi++)
#pragma unroll
            for (int ni = 0; ni < 4; ni++)
#pragma unroll
                for (int j = 0; j < 4; j++) acc[mi][ni][j] = 0.f;

        const int chunks = K >> 6;

#define ISSUE(chunk, slot)                                                        \
        do {                                                                      \
            int _kk = (chunk) << 6;                                               \
            uint32_t _aO = asb + (uint32_t)(slot) * BUFBY;                        \
            uint32_t _bO = bsb + (uint32_t)(slot) * BUFBY;                        \
            _Pragma("unroll")                                                     \
            for (int _p = 0; _p < 4; _p++) {                                      \
                int _row = srow + _p * 32;                                        \
                int _av  = (rowTile + _row) < Mloc ? 16 : 0;                      \
                cp16(_aO + (uint32_t)(_row * ROWB + sseg * 2),                    \
                     A + (size_t)(rowTile + _row) * K + _kk + sseg, _av);         \
                cp16(_bO + (uint32_t)(_row * ROWB + sseg * 2),                    \
                     Wt + (size_t)(colTile + _row) * K + _kk + sseg, 16);         \
            }                                                                     \
            cp_commit();                                                          \
        } while (0)

        ISSUE(0, 0);
        ISSUE(1, 1);

        int sCur = 0;
        for (int i = 0; i < chunks; i++) {
            if (i + 1 < chunks) cp_wait<1>();
            else                cp_wait<0>();
            __syncthreads();
            if (i + 2 < chunks) {
                int slot = sCur + 2; if (slot >= STAGES) slot -= STAGES;
                ISSUE(i + 2, slot);
            }
            uint32_t aBuf = asb + (uint32_t)sCur * BUFBY;
            uint32_t bBuf = bsb + (uint32_t)sCur * BUFBY;
#pragma unroll
            for (int kb = 0; kb < 64; kb += 16) {
                uint32_t af[4][4], bfr[4][2];
#pragma unroll
                for (int mi = 0; mi < 4; mi++)
                    ldsm_x4(af[mi], aBuf + (uint32_t)((warpM * 64 + mi * 16) * ROWB + kb * 2 + aoffB));
#pragma unroll
                for (int ni = 0; ni < 4; ni++)
                    ldsm_x2(bfr[ni], bBuf + (uint32_t)((warpN * 32 + ni * 8) * ROWB + kb * 2 + boffB));
#pragma unroll
                for (int mi = 0; mi < 4; mi++)
#pragma unroll
                    for (int ni = 0; ni < 4; ni++)
                        mma_bf16(acc[mi][ni], af[mi], bfr[ni]);
            }
            if (++sCur == STAGES) sCur = 0;
        }
#undef ISSUE

        // ---- domain MIX: wait shared-MIX columns before RMW of out ----
        if (task == TASK_MIX && dom) {
            if (tid == 0) spin_ge(&g_colCnt[bx], 64);
            __syncthreads();
            __threadfence();
        }

        // ---- epilogue ----
#pragma unroll
        for (int mi = 0; mi < 4; mi++)
#pragma unroll
            for (int h = 0; h < 2; h++) {
                int lr = rowTile + warpM * 64 + mi * 16 + grp + h * 8;
                if (lr >= Mloc) continue;
                int grow = dom ? rowBase + lr : lr;
#pragma unroll
                for (int ni = 0; ni < 4; ni++) {
                    int col = colTile + warpN * 32 + ni * 8 + t4 * 2;
                    float v0 = acc[mi][ni][h * 2 + 0];
                    float v1 = acc[mi][ni][h * 2 + 1];
                    if (task == TASK_ACT) {
                        float a0 = v0 + bias[col];
                        float a1 = v1 + bias[col + 1];
                        a0 = 0.5f * a0 * (1.0f + erff(a0 * 0.70710678118654752f));
                        a1 = 0.5f * a1 * (1.0f + erff(a1 * 0.70710678118654752f));
                        union { __nv_bfloat162 h2; uint32_t u; } cv;
                        cv.h2 = __floats2bfloat162_rn(a0, a1);
                        *(uint32_t*)((dom ? g_Ad : g_Ab) + (size_t)grow * FFN + col) = cv.u;
                    } else if (task == TASK_GATE) {
                        float* dst = (dom ? g_Gd : g_G) + (size_t)grow * DIM + col;
                        dst[0] = 1.0f / (1.0f + expf(-(v0 + bias[col])));
                        dst[1] = 1.0f / (1.0f + expf(-(v1 + bias[col + 1])));
                    } else {
                        const float* xp = (dom ? g_Xg : xf) + (size_t)grow * DIM + col;
                        const float* gp = (dom ? g_Gd : g_G) + (size_t)grow * DIM + col;
                        float x0 = xp[0], x1 = xp[1];
                        float h0 = v0 + bias[col]     + x0;
                        float h1 = v1 + bias[col + 1] + x1;
                        float g0 = gp[0], g1 = gp[1];
                        float o0 = g0 * h0 + (1.0f - g0) * x0;
                        float o1 = g1 * h1 + (1.0f - g1) * x1;
                        if (!dom) {
                            float* dst = out + (size_t)grow * DIM + col;
                            dst[0] = o0;
                            dst[1] = o1;
                        } else {
                            float* dst = out + (size_t)g_perm[grow] * DIM + col;
                            dst[0] += o0;          // unique writer per (token,col)
                            dst[1] += o1;
                        }
                    }
                }
            }

        // ---- release signals ----
        if (task != TASK_MIX) {
            __threadfence();
            __syncthreads();
            if (tid == 0) atomicAdd(&g_rowCnt[gy], 1);
        } else if (!dom) {
            __threadfence();
            __syncthreads();
            if (tid == 0) atomicAdd(&g_colCnt[bx], 1);
        }
    }
}

// ---------------- launch -----------------------------------------------------
extern "C" void kernel_launch(void* const* d_in, const int* in_sizes, int n_in,
                              void* d_out, int out_size)
{
    const float* x   = (const float*)d_in[0];
    const int*   ids = (const int*)  d_in[1];
    const float* sW1 = (const float*)d_in[2];
    const float* sb1 = (const float*)d_in[3];
    const float* sW2 = (const float*)d_in[4];
    const float* sb2 = (const float*)d_in[5];
    const float* sWg = (const float*)d_in[6];
    const float* sbg = (const float*)d_in[7];
    const float* dW1 = (const float*)d_in[8];
    const float* db1 = (const float*)d_in[9];
    const float* dW2 = (const float*)d_in[10];
    const float* db2 = (const float*)d_in[11];
    const float* dWg = (const float*)d_in[12];
    const float* dbg = (const float*)d_in[13];
    float* out = (float*)d_out;

    cudaFuncSetAttribute(gemm_persist, cudaFuncAttributeMaxDynamicSharedMemorySize, SMEM_BYTES);

    // routing + converts
    k_zero     <<<1, 256>>>();
    k_count_cvt<<<NTOK * DIM / 4 / 256, 256>>>(ids, x);
    k_scan     <<<1, 32>>>();
    k_scatter  <<<NTOK / 256, 256>>>(ids);
    k_gather   <<<NTOK, 256>>>(x);

    // all weight transposes+converts in one full-chip launch (DRAM-floor ~80us)
    k_transpose_all<<<101376, dim3(32, 8)>>>(sW1, sW2, sWg, dW1, dW2, dWg);

    // ONE persistent launch: GEMM1 acts + gate + GEMM2/mix (fused combine)
    gemm_persist<<<304, 256, SMEM_BYTES>>>(x, sb1, db1, sbg, dbg, sb2, db2, out);
}

// round 16
// speedup vs baseline: 1.0155x; 1.0155x over previous
#include <cuda_runtime.h>
#include <cuda_bf16.h>
#include <math.h>
#include <stdint.h>

#define NTOK 8192
#define DIM  1024
#define FFN  4096
#define NE   10
#define NROW_MAX 140

typedef __nv_bfloat16 bf16;

// ---------------- scratch (device globals: no allocation allowed) ----------
__device__ bf16  g_Ab [(size_t)NTOK * FFN];   // shared gelu acts (token rows)
__device__ bf16  g_Ad [(size_t)NTOK * FFN];   // domain gelu acts (perm rows)
__device__ float g_G  [(size_t)NTOK * DIM];   // shared gate values (token rows)
__device__ float g_Gd [(size_t)NTOK * DIM];   // domain gate values (perm rows)
__device__ float g_Od [(size_t)NTOK * DIM];   // domain mix output (perm rows)
__device__ float g_P  [(size_t)2 * NTOK * DIM]; // MIX half-K partials (sh | dom)
__device__ float g_Xg [(size_t)NTOK * DIM];   // gathered x fp32 (perm rows)
__device__ bf16  g_Xb [(size_t)NTOK * DIM];   // x bf16 (token rows)
__device__ bf16  g_Xgb[(size_t)NTOK * DIM];   // gathered x bf16 (perm rows)
__device__ int   g_perm[NTOK];
__device__ int   g_cnt[NE];
__device__ int   g_off[NE];
__device__ int   g_tileTab[80];
__device__ int   g_ntile;
__device__ int   g_task;                      // persistent task counter
__device__ int   g_rowCnt[160];               // per-row-group producer counters
__device__ int   g_mixCnt[NROW_MAX * 8];      // per-MIX-tile half-A counters

// transposed bf16 weights: Wt[n*K + k] = bf16(W[k*N + n])
__device__ bf16 g_sW1t[(size_t)FFN * DIM];
__device__ bf16 g_sW2t[(size_t)DIM * FFN];
__device__ bf16 g_sWgt[(size_t)DIM * DIM];
__device__ bf16 g_dW1t[(size_t)NE * FFN * DIM];
__device__ bf16 g_dW2t[(size_t)NE * DIM * FFN];
__device__ bf16 g_dWgt[(size_t)NE * DIM * DIM];

// gemm task layout: rows 0..137 (64 shared + 74 domain slots)
//   t in [0, 5520):            r=t/40, c=t%40; c<32 -> ACT (r,c); else GATE (r,c-32)
//   t in [5520, 6624):  MIX-A  u=t-5520; gy=u>>3, bx=u&7; k chunks [0,32)
//   t in [6624, 7728):  MIX-B  u=t-6624; gy=u>>3, bx=u&7; k chunks [32,64)
#define NROW       138
#define TASK_PROD  (NROW * 40)
#define NMIX       (NROW * 8)
#define TASK_TOTAL (TASK_PROD + 2 * NMIX)
#define DEP_TARGET 40

// ---------------- PTX helpers ------------------------------------------------
__device__ __forceinline__ uint32_t smem_u32(const void* p) {
    uint32_t a;
    asm("{ .reg .u64 t; cvta.to.shared.u64 t, %1; cvt.u32.u64 %0, t; }" : "=r"(a) : "l"(p));
    return a;
}
__device__ __forceinline__ void cp16(uint32_t dst, const void* src, int srcbytes) {
    asm volatile("cp.async.cg.shared.global [%0], [%1], 16, %2;"
                 :: "r"(dst), "l"(src), "r"(srcbytes) : "memory");
}
__device__ __forceinline__ void cp_commit() {
    asm volatile("cp.async.commit_group;" ::: "memory");
}
template <int N>
__device__ __forceinline__ void cp_wait() {
    asm volatile("cp.async.wait_group %0;" :: "n"(N) : "memory");
}
__device__ __forceinline__ void ldsm_x4(uint32_t* r, uint32_t addr) {
    asm volatile("ldmatrix.sync.aligned.m8n8.x4.shared.b16 {%0,%1,%2,%3}, [%4];"
                 : "=r"(r[0]), "=r"(r[1]), "=r"(r[2]), "=r"(r[3]) : "r"(addr));
}
__device__ __forceinline__ void ldsm_x2(uint32_t* r, uint32_t addr) {
    asm volatile("ldmatrix.sync.aligned.m8n8.x2.shared.b16 {%0,%1}, [%2];"
                 : "=r"(r[0]), "=r"(r[1]) : "r"(addr));
}
__device__ __forceinline__ void mma_bf16(float* c, const uint32_t* a, const uint32_t* b) {
    asm volatile(
        "mma.sync.aligned.m16n8k16.row.col.f32.bf16.bf16.f32 "
        "{%0,%1,%2,%3},{%4,%5,%6,%7},{%8,%9},{%0,%1,%2,%3};"
        : "+f"(c[0]), "+f"(c[1]), "+f"(c[2]), "+f"(c[3])
        : "r"(a[0]), "r"(a[1]), "r"(a[2]), "r"(a[3]), "r"(b[0]), "r"(b[1]));
}
__device__ __forceinline__ void spin_ge(volatile int* p, int tgt) {
    while (*p < tgt) __nanosleep(64);
}

// ---------------- routing + converts -----------------------------------------
__global__ void k_zero() {
    int i = threadIdx.x;
    if (i < NE)  g_cnt[i] = 0;
    if (i < 160) g_rowCnt[i] = 0;
    for (int j = i; j < NROW_MAX * 8; j += 256) g_mixCnt[j] = 0;
    if (i == 255) g_task = 0;
}
__global__ void k_count_cvt(const int* __restrict__ ids, const float* __restrict__ x) {
    int i = blockIdx.x * blockDim.x + threadIdx.x;
    float4 v = ((const float4*)x)[i];
    union { __nv_bfloat162 h; uint32_t u; } a, b;
    a.h = __floats2bfloat162_rn(v.x, v.y);
    b.h = __floats2bfloat162_rn(v.z, v.w);
    ((uint2*)g_Xb)[i] = make_uint2(a.u, b.u);
    if (i < NTOK) atomicAdd(&g_cnt[ids[i]], 1);
}
// merged scan + scatter (single block, smem atomics)
__global__ void k_scan_scatter(const int* __restrict__ ids) {
    __shared__ int sOff[NE], sCur[NE];
    int tid = threadIdx.x;
    if (tid == 0) {
        int s = 0;
        for (int e = 0; e < NE; e++) { g_off[e] = s; sOff[e] = s; s += g_cnt[e]; }
        int t = 0;
        for (int e = 0; e < NE; e++) {
            int nt = (g_cnt[e] + 127) >> 7;
            for (int q = 0; q < nt; q++) g_tileTab[t++] = (e << 16) | q;
        }
        g_ntile = t;
    }
    if (tid < NE) sCur[tid] = 0;
    __syncthreads();
    for (int i = tid; i < NTOK; i += 256) {
        int e = ids[i];
        int p = sOff[e] + atomicAdd(&sCur[e], 1);
        g_perm[p] = i;
    }
}
__global__ void k_gather(const float* __restrict__ x) {
    int p   = blockIdx.x;
    int src = g_perm[p];
    float4 v = ((const float4*)(x + (size_t)src * DIM))[threadIdx.x];
    ((float4*)(g_Xg + (size_t)p * DIM))[threadIdx.x] = v;
    union { __nv_bfloat162 h; uint32_t u; } a, b;
    a.h = __floats2bfloat162_rn(v.x, v.y);
    b.h = __floats2bfloat162_rn(v.z, v.w);
    ((uint2*)(g_Xgb + (size_t)p * DIM))[threadIdx.x] = make_uint2(a.u, b.u);
}
__global__ void k_combine(float* __restrict__ out) {
    int p = blockIdx.x;
    int t = g_perm[p];
    float4* o = (float4*)(out + (size_t)t * DIM);
    const float4* s = (const float4*)(g_Od + (size_t)p * DIM);
    float4 a = o[threadIdx.x], b = s[threadIdx.x];
    a.x += b.x; a.y += b.y; a.z += b.z; a.w += b.w;
    o[threadIdx.x] = a;
}

// ---------------- single merged transpose+convert launch ---------------------
__global__ void k_transpose_all(
    const float* __restrict__ sW1, const float* __restrict__ sW2,
    const float* __restrict__ sWg, const float* __restrict__ dW1,
    const float* __restrict__ dW2, const float* __restrict__ dWg)
{
    int b = blockIdx.x;
    const float* W; bf16* Wt; int K, N;
    if (b < 4096)                { W = sW1; Wt = g_sW1t; K = DIM; N = FFN; }
    else if ((b -= 4096) < 4096) { W = sW2; Wt = g_sW2t; K = FFN; N = DIM; }
    else if ((b -= 4096) < 1024) { W = sWg; Wt = g_sWgt; K = DIM; N = DIM; }
    else if ((b -= 1024) < 40960) {
        int e = b / 4096; b -= e * 4096;
        W = dW1 + (size_t)e * DIM * FFN; Wt = g_dW1t + (size_t)e * DIM * FFN;
        K = DIM; N = FFN;
    }
    else if ((b -= 40960) < 40960) {
        int e = b / 4096; b -= e * 4096;
        W = dW2 + (size_t)e * DIM * FFN; Wt = g_dW2t + (size_t)e * DIM * FFN;
        K = FFN; N = DIM;
    }
    else {
        b -= 40960;
        int e = b / 1024; b -= e * 1024;
        W = dWg + (size_t)e * DIM * DIM; Wt = g_dWgt + (size_t)e * DIM * DIM;
        K = DIM; N = DIM;
    }
    int nb = N >> 5;
    int n0 = (b % nb) * 32, k0 = (b / nb) * 32;

    __shared__ float t[32][33];
#pragma unroll
    for (int i = threadIdx.y; i < 32; i += 8)
        t[i][threadIdx.x] = W[(size_t)(k0 + i) * N + n0 + threadIdx.x];
    __syncthreads();
#pragma unroll
    for (int i = threadIdx.y; i < 32; i += 8)
        Wt[(size_t)(n0 + i) * K + k0 + threadIdx.x] = __float2bfloat16(t[threadIdx.x][i]);
}

// ---------------- persistent fused GEMM --------------------------------------
#define ROWB   144
#define BUFBY  (128 * ROWB)
#define STAGES 3
#define SMEM_BYTES (STAGES * 2 * BUFBY)

#define TASK_ACT  0
#define TASK_GATE 1
#define TASK_MIXA 2
#define TASK_MIXB 3

__device__ __forceinline__ bool dom_tile(int idx, int& e, int& Mloc,
                                         int& rowBase, int& rowTile) {
    if (idx >= g_ntile) return false;
    int pk  = g_tileTab[idx];
    e       = pk >> 16;
    rowTile = (pk & 0xffff) * 128;
    Mloc    = g_cnt[e];
    rowBase = g_off[e];
    return true;
}

__global__ void __launch_bounds__(256, 2) gemm_persist(
    const float* __restrict__ xf,
    const float* __restrict__ sb1, const float* __restrict__ db1,
    const float* __restrict__ sbg, const float* __restrict__ dbg,
    const float* __restrict__ sb2, const float* __restrict__ db2,
    float* __restrict__ out)
{
    extern __shared__ uint8_t sm[];
    __shared__ int s_task;
    uint32_t asb = smem_u32(sm);
    uint32_t bsb = asb + STAGES * BUFBY;

    int tid   = threadIdx.x;
    int lane  = tid & 31;
    int warp  = tid >> 5;
    int warpM = warp >> 2;
    int warpN = warp & 3;

    int srow = tid >> 3;
    int sseg = (tid & 7) * 8;
    int aoffB = (lane & 15) * ROWB + ((lane >> 4) << 4);
    int boffB = (lane & 7)  * ROWB + (((lane >> 3) & 1) << 4);
    int grp = lane >> 2, t4 = lane & 3;

    for (;;) {
        if (tid == 0) s_task = atomicAdd(&g_task, 1);
        __syncthreads();                  // all warps done with prior tile's smem
        int t = s_task;
        if (t >= TASK_TOTAL) return;

        // ---- decode ----
        int task, gy, bx;
        if (t < TASK_PROD) {
            gy = t / 40; int c = t - gy * 40;
            if (c < 32) { task = TASK_ACT;  bx = c; }
            else        { task = TASK_GATE; bx = c - 32; }
        } else if (t < TASK_PROD + NMIX) {
            int u = t - TASK_PROD;
            task = TASK_MIXA; gy = u >> 3; bx = u & 7;
        } else {
            int u = t - TASK_PROD - NMIX;
            task = TASK_MIXB; gy = u >> 3; bx = u & 7;
        }

        bool dom = gy >= 64;
        int e = 0, Mloc = NTOK, rowBase = 0, rowTile = 0;
        if (!dom) rowTile = gy * 128;
        else if (!dom_tile(gy - 64, e, Mloc, rowBase, rowTile)) continue;

        const bf16 *A, *Wt;
        const float* bias;
        int K, kbase, chunks;
        if (task == TASK_ACT) {
            K = DIM; kbase = 0; chunks = 16;
            A    = dom ? g_Xgb + (size_t)rowBase * K : g_Xb;
            Wt   = dom ? g_dW1t + (size_t)e * (size_t)K * FFN : g_sW1t;
            bias = dom ? db1 + (size_t)e * FFN : sb1;
        } else if (task == TASK_GATE) {
            K = DIM; kbase = 0; chunks = 16;
            A    = dom ? g_Xgb + (size_t)rowBase * K : g_Xb;
            Wt   = dom ? g_dWgt + (size_t)e * (size_t)K * DIM : g_sWgt;
            bias = dom ? dbg + (size_t)e * DIM : sbg;
        } else {
            K = FFN; chunks = 32;
            kbase = (task == TASK_MIXA) ? 0 : 32;
            A    = (dom ? g_Ad : g_Ab) + (dom ? (size_t)rowBase * K : 0);
            Wt   = dom ? g_dW2t + (size_t)e * (size_t)K * DIM : g_sW2t;
            bias = dom ? db2 + (size_t)e * DIM : sb2;
            if (tid == 0) {
                spin_ge(&g_rowCnt[gy], DEP_TARGET);           // producers of this row
                if (task == TASK_MIXB) spin_ge(&g_mixCnt[gy * 8 + bx], 1);
            }
            __syncthreads();
            __threadfence();              // acquire
        }

        int colTile = bx * 128;

        float acc[4][4][4];
#pragma unroll
        for (int mi = 0; mi < 4; mi++)
#pragma unroll
            for (int ni = 0; ni < 4; ni++)
#pragma unroll
                for (int j = 0; j < 4; j++) acc[mi][ni][j] = 0.f;

#define ISSUE(chunk, slot)                                                        \
        do {                                                                      \
            int _kk = (kbase + (chunk)) << 6;                                     \
            uint32_t _aO = asb + (uint32_t)(slot) * BUFBY;                        \
            uint32_t _bO = bsb + (uint32_t)(slot) * BUFBY;                        \
            _Pragma("unroll")                                                     \
            for (int _p = 0; _p < 4; _p++) {                                      \
                int _row = srow + _p * 32;                                        \
                int _av  = (rowTile + _row) < Mloc ? 16 : 0;                      \
                cp16(_aO + (uint32_t)(_row * ROWB + sseg * 2),                    \
                     A + (size_t)(rowTile + _row) * K + _kk + sseg, _av);         \
                cp16(_bO + (uint32_t)(_row * ROWB + sseg * 2),                    \
                     Wt + (size_t)(colTile + _row) * K + _kk + sseg, 16);         \
            }                                                                     \
            cp_commit();                                                          \
        } while (0)

        ISSUE(0, 0);
        ISSUE(1, 1);

        int sCur = 0;
        for (int i = 0; i < chunks; i++) {
            if (i + 1 < chunks) cp_wait<1>();
            else                cp_wait<0>();
            __syncthreads();
            if (i + 2 < chunks) {
                int slot = sCur + 2; if (slot >= STAGES) slot -= STAGES;
                ISSUE(i + 2, slot);
            }
            uint32_t aBuf = asb + (uint32_t)sCur * BUFBY;
            uint32_t bBuf = bsb + (uint32_t)sCur * BUFBY;
#pragma unroll
            for (int kb = 0; kb < 64; kb += 16) {
                uint32_t af[4][4], bfr[4][2];
#pragma unroll
                for (int mi = 0; mi < 4; mi++)
                    ldsm_x4(af[mi], aBuf + (uint32_t)((warpM * 64 + mi * 16) * ROWB + kb * 2 + aoffB));
#pragma unroll
                for (int ni = 0; ni < 4; ni++)
                    ldsm_x2(bfr[ni], bBuf + (uint32_t)((warpN * 32 + ni * 8) * ROWB + kb * 2 + boffB));
#pragma unroll
                for (int mi = 0; mi < 4; mi++)
#pragma unroll
                    for (int ni = 0; ni < 4; ni++)
                        mma_bf16(acc[mi][ni], af[mi], bfr[ni]);
            }
            if (++sCur == STAGES) sCur = 0;
        }
#undef ISSUE

        // ---- epilogue ----
        float* Pbase = g_P + (dom ? (size_t)NTOK * DIM : 0);
#pragma unroll
        for (int mi = 0; mi < 4; mi++)
#pragma unroll
            for (int h = 0; h < 2; h++) {
                int lr = rowTile + warpM * 64 + mi * 16 + grp + h * 8;
                if (lr >= Mloc) continue;
                int grow = dom ? rowBase + lr : lr;
#pragma unroll
                for (int ni = 0; ni < 4; ni++) {
                    int col = colTile + warpN * 32 + ni * 8 + t4 * 2;
                    float v0 = acc[mi][ni][h * 2 + 0];
                    float v1 = acc[mi][ni][h * 2 + 1];
                    if (task == TASK_ACT) {
                        float a0 = v0 + bias[col];
                        float a1 = v1 + bias[col + 1];
                        a0 = 0.5f * a0 * (1.0f + erff(a0 * 0.70710678118654752f));
                        a1 = 0.5f * a1 * (1.0f + erff(a1 * 0.70710678118654752f));
                        union { __nv_bfloat162 h2; uint32_t u; } cv;
                        cv.h2 = __floats2bfloat162_rn(a0, a1);
                        *(uint32_t*)((dom ? g_Ad : g_Ab) + (size_t)grow * FFN + col) = cv.u;
                    } else if (task == TASK_GATE) {
                        float* dst = (dom ? g_Gd : g_G) + (size_t)grow * DIM + col;
                        dst[0] = 1.0f / (1.0f + expf(-(v0 + bias[col])));
                        dst[1] = 1.0f / (1.0f + expf(-(v1 + bias[col + 1])));
                    } else if (task == TASK_MIXA) {
                        float* dst = Pbase + (size_t)grow * DIM + col;
                        dst[0] = v0;                  // raw half-K partial
                        dst[1] = v1;
                    } else {  // TASK_MIXB: add partial, finish h, gate-mix
                        const float* pp = Pbase + (size_t)grow * DIM + col;
                        v0 += pp[0];
                        v1 += pp[1];
                        const float* xp = (dom ? g_Xg : xf) + (size_t)grow * DIM + col;
                        const float* gp = (dom ? g_Gd : g_G) + (size_t)grow * DIM + col;
                        float x0 = xp[0], x1 = xp[1];
                        float h0 = v0 + bias[col]     + x0;
                        float h1 = v1 + bias[col + 1] + x1;
                        float g0 = gp[0], g1 = gp[1];
                        float o0 = g0 * h0 + (1.0f - g0) * x0;
                        float o1 = g1 * h1 + (1.0f - g1) * x1;
                        float* dst = (dom ? g_Od + (size_t)grow * DIM
                                          : out + (size_t)grow * DIM) + col;
                        dst[0] = o0;
                        dst[1] = o1;
                    }
                }
            }

        // ---- release signals ----
        if (task == TASK_ACT || task == TASK_GATE) {
            __threadfence();
            __syncthreads();
            if (tid == 0) atomicAdd(&g_rowCnt[gy], 1);
        } else if (task == TASK_MIXA) {
            __threadfence();
            __syncthreads();
            if (tid == 0) atomicAdd(&g_mixCnt[gy * 8 + bx], 1);
        }
    }
}

// ---------------- launch -----------------------------------------------------
extern "C" void kernel_launch(void* const* d_in, const int* in_sizes, int n_in,
                              void* d_out, int out_size)
{
    const float* x   = (const float*)d_in[0];
    const int*   ids = (const int*)  d_in[1];
    const float* sW1 = (const float*)d_in[2];
    const float* sb1 = (const float*)d_in[3];
    const float* sW2 = (const float*)d_in[4];
    const float* sb2 = (const float*)d_in[5];
    const float* sWg = (const float*)d_in[6];
    const float* sbg = (const float*)d_in[7];
    const float* dW1 = (const float*)d_in[8];
    const float* db1 = (const float*)d_in[9];
    const float* dW2 = (const float*)d_in[10];
    const float* db2 = (const float*)d_in[11];
    const float* dWg = (const float*)d_in[12];
    const float* dbg = (const float*)d_in[13];
    float* out = (float*)d_out;

    cudaFuncSetAttribute(gemm_persist, cudaFuncAttributeMaxDynamicSharedMemorySize, SMEM_BYTES);

    // routing + converts
    k_zero        <<<1, 256>>>();
    k_count_cvt   <<<NTOK * DIM / 4 / 256, 256>>>(ids, x);
    k_scan_scatter<<<1, 256>>>(ids);
    k_gather      <<<NTOK, 256>>>(x);

    // all weight transposes+converts in one full-chip launch (DRAM floor ~80us)
    k_transpose_all<<<101376, dim3(32, 8)>>>(sW1, sW2, sWg, dW1, dW2, dWg);

    // ONE persistent launch: ACT + GATE + split-K MIX via task queue
    gemm_persist<<<304, 256, SMEM_BYTES>>>(x, sb1, db1, sbg, dbg, sb2, db2, out);

    // Combine: out[perm[p]] += domain mix
    k_combine<<<NTOK, 256>>>(out);
}

// round 17
// speedup vs baseline: 1.0417x; 1.0258x over previous
#include <cuda_runtime.h>
#include <cuda_bf16.h>
#include <math.h>
#include <stdint.h>

#define NTOK 8192
#define DIM  1024
#define FFN  4096
#define NE   10

typedef __nv_bfloat16 bf16;

// ---------------- scratch (device globals: no allocation allowed) ----------
__device__ bf16  g_Ab [(size_t)NTOK * FFN];   // shared gelu acts (token rows)
__device__ bf16  g_Ad [(size_t)NTOK * FFN];   // domain gelu acts (perm rows)
__device__ float g_G  [(size_t)NTOK * DIM];   // shared gate values (token rows)
__device__ float g_Gd [(size_t)NTOK * DIM];   // domain gate values (perm rows)
__device__ float g_Od [(size_t)NTOK * DIM];   // domain mix output (perm rows)
__device__ float g_Xg [(size_t)NTOK * DIM];   // gathered x fp32 (perm rows)
__device__ bf16  g_Xb [(size_t)NTOK * DIM];   // x bf16 (token rows)
__device__ bf16  g_Xgb[(size_t)NTOK * DIM];   // gathered x bf16 (perm rows)
__device__ int   g_perm[NTOK];
__device__ int   g_cnt[NE];
__device__ int   g_off[NE];
__device__ int   g_tileTab[80];
__device__ int   g_ntile;
__device__ int   g_task;                      // persistent task counter
__device__ int   g_rowCnt[160];               // per-row-group producer counters

// transposed bf16 weights: Wt[n*K + k] = bf16(W[k*N + n])
__device__ bf16 g_sW1t[(size_t)FFN * DIM];
__device__ bf16 g_sW2t[(size_t)DIM * FFN];
__device__ bf16 g_sWgt[(size_t)DIM * DIM];
__device__ bf16 g_dW1t[(size_t)NE * FFN * DIM];
__device__ bf16 g_dW2t[(size_t)NE * DIM * FFN];
__device__ bf16 g_dWgt[(size_t)NE * DIM * DIM];

// gemm task layout: rows 0..137 (64 shared + 74 domain slots)
//   t in [0, 5520): r=t/40, c=t%40; c<32 -> ACT (r,c); else GATE (r,c-32)
//   t in [5520, 6624): MIX (gy=u>>3, bx=u&7)
#define NROW       138
#define TASK_PROD  (NROW * 40)
#define TASK_TOTAL (TASK_PROD + NROW * 8)
#define DEP_TARGET 40

// merged prep launch: blocks [0, 8192) = x convert + count; rest = transposes
#define CVT_BLOCKS 8192
#define PREP_BLOCKS (CVT_BLOCKS + 101376)

// ---------------- PTX helpers ------------------------------------------------
__device__ __forceinline__ uint32_t smem_u32(const void* p) {
    uint32_t a;
    asm("{ .reg .u64 t; cvta.to.shared.u64 t, %1; cvt.u32.u64 %0, t; }" : "=r"(a) : "l"(p));
    return a;
}
__device__ __forceinline__ void cp16(uint32_t dst, const void* src, int srcbytes) {
    asm volatile("cp.async.cg.shared.global [%0], [%1], 16, %2;"
                 :: "r"(dst), "l"(src), "r"(srcbytes) : "memory");
}
__device__ __forceinline__ void cp_commit() {
    asm volatile("cp.async.commit_group;" ::: "memory");
}
template <int N>
__device__ __forceinline__ void cp_wait() {
    asm volatile("cp.async.wait_group %0;" :: "n"(N) : "memory");
}
__device__ __forceinline__ void ldsm_x4(uint32_t* r, uint32_t addr) {
    asm volatile("ldmatrix.sync.aligned.m8n8.x4.shared.b16 {%0,%1,%2,%3}, [%4];"
                 : "=r"(r[0]), "=r"(r[1]), "=r"(r[2]), "=r"(r[3]) : "r"(addr));
}
__device__ __forceinline__ void ldsm_x2(uint32_t* r, uint32_t addr) {
    asm volatile("ldmatrix.sync.aligned.m8n8.x2.shared.b16 {%0,%1}, [%2];"
                 : "=r"(r[0]), "=r"(r[1]) : "r"(addr));
}
__device__ __forceinline__ void mma_bf16(float* c, const uint32_t* a, const uint32_t* b) {
    asm volatile(
        "mma.sync.aligned.m16n8k16.row.col.f32.bf16.bf16.f32 "
        "{%0,%1,%2,%3},{%4,%5,%6,%7},{%8,%9},{%0,%1,%2,%3};"
        : "+f"(c[0]), "+f"(c[1]), "+f"(c[2]), "+f"(c[3])
        : "r"(a[0]), "r"(a[1]), "r"(a[2]), "r"(a[3]), "r"(b[0]), "r"(b[1]));
}
__device__ __forceinline__ void spin_ge(volatile int* p, int tgt) {
    while (*p < tgt) __nanosleep(64);
}

// ---------------- routing ----------------------------------------------------
__global__ void k_zero() {
    int i = threadIdx.x;
    if (i < NE)  g_cnt[i] = 0;
    if (i < 160) g_rowCnt[i] = 0;
    if (i == 255) g_task = 0;
}

// merged prep: x convert + histogram (blocks < CVT_BLOCKS) | weight transposes
__global__ void k_prep(
    const int* __restrict__ ids, const float* __restrict__ x,
    const float* __restrict__ sW1, const float* __restrict__ sW2,
    const float* __restrict__ sWg, const float* __restrict__ dW1,
    const float* __restrict__ dW2, const float* __restrict__ dWg)
{
    int b = blockIdx.x;
    int tx = threadIdx.x, ty = threadIdx.y;
    int tid = ty * 32 + tx;

    if (b < CVT_BLOCKS) {
        // x convert (float4 per thread) + token histogram
        int i = b * 256 + tid;               // over NTOK*DIM/4 float4s
        float4 v = ((const float4*)x)[i];
        union { __nv_bfloat162 h; uint32_t u; } a2, b2;
        a2.h = __floats2bfloat162_rn(v.x, v.y);
        b2.h = __floats2bfloat162_rn(v.z, v.w);
        ((uint2*)g_Xb)[i] = make_uint2(a2.u, b2.u);
        if (i < NTOK) atomicAdd(&g_cnt[ids[i]], 1);
        return;
    }
    b -= CVT_BLOCKS;

    const float* W; bf16* Wt; int K, N;
    if (b < 4096)                { W = sW1; Wt = g_sW1t; K = DIM; N = FFN; }
    else if ((b -= 4096) < 4096) { W = sW2; Wt = g_sW2t; K = FFN; N = DIM; }
    else if ((b -= 4096) < 1024) { W = sWg; Wt = g_sWgt; K = DIM; N = DIM; }
    else if ((b -= 1024) < 40960) {
        int e = b / 4096; b -= e * 4096;
        W = dW1 + (size_t)e * DIM * FFN; Wt = g_dW1t + (size_t)e * DIM * FFN;
        K = DIM; N = FFN;
    }
    else if ((b -= 40960) < 40960) {
        int e = b / 4096; b -= e * 4096;
        W = dW2 + (size_t)e * DIM * FFN; Wt = g_dW2t + (size_t)e * DIM * FFN;
        K = FFN; N = DIM;
    }
    else {
        b -= 40960;
        int e = b / 1024; b -= e * 1024;
        W = dWg + (size_t)e * DIM * DIM; Wt = g_dWgt + (size_t)e * DIM * DIM;
        K = DIM; N = DIM;
    }
    int nb = N >> 5;
    int n0 = (b % nb) * 32, k0 = (b / nb) * 32;

    __shared__ float t[32][33];
#pragma unroll
    for (int i = ty; i < 32; i += 8)
        t[i][tx] = W[(size_t)(k0 + i) * N + n0 + tx];
    __syncthreads();
#pragma unroll
    for (int i = ty; i < 32; i += 8)
        Wt[(size_t)(n0 + i) * K + k0 + tx] = __float2bfloat16(t[tx][i]);
}

// merged scan + scatter (single block, smem atomics)
__global__ void k_scan_scatter(const int* __restrict__ ids) {
    __shared__ int sOff[NE], sCur[NE];
    int tid = threadIdx.x;
    if (tid == 0) {
        int s = 0;
        for (int e = 0; e < NE; e++) { g_off[e] = s; sOff[e] = s; s += g_cnt[e]; }
        int t = 0;
        for (int e = 0; e < NE; e++) {
            int nt = (g_cnt[e] + 127) >> 7;
            for (int q = 0; q < nt; q++) g_tileTab[t++] = (e << 16) | q;
        }
        g_ntile = t;
    }
    if (tid < NE) sCur[tid] = 0;
    __syncthreads();
    for (int i = tid; i < NTOK; i += 256) {
        int e = ids[i];
        int p = sOff[e] + atomicAdd(&sCur[e], 1);
        g_perm[p] = i;
    }
}
__global__ void k_gather(const float* __restrict__ x) {
    int p   = blockIdx.x;
    int src = g_perm[p];
    float4 v = ((const float4*)(x + (size_t)src * DIM))[threadIdx.x];
    ((float4*)(g_Xg + (size_t)p * DIM))[threadIdx.x] = v;
    union { __nv_bfloat162 h; uint32_t u; } a, b;
    a.h = __floats2bfloat162_rn(v.x, v.y);
    b.h = __floats2bfloat162_rn(v.z, v.w);
    ((uint2*)(g_Xgb + (size_t)p * DIM))[threadIdx.x] = make_uint2(a.u, b.u);
}
__global__ void k_combine(float* __restrict__ out) {
    int p = blockIdx.x;
    int t = g_perm[p];
    float4* o = (float4*)(out + (size_t)t * DIM);
    const float4* s = (const float4*)(g_Od + (size_t)p * DIM);
    float4 a = o[threadIdx.x], b = s[threadIdx.x];
    a.x += b.x; a.y += b.y; a.z += b.z; a.w += b.w;
    o[threadIdx.x] = a;
}

// ---------------- persistent fused GEMM (R12-proven) --------------------------
#define ROWB   144
#define BUFBY  (128 * ROWB)
#define STAGES 3
#define SMEM_BYTES (STAGES * 2 * BUFBY)

#define TASK_ACT  0
#define TASK_GATE 1
#define TASK_MIX  2

__device__ __forceinline__ bool dom_tile(int idx, int& e, int& Mloc,
                                         int& rowBase, int& rowTile) {
    if (idx >= g_ntile) return false;
    int pk  = g_tileTab[idx];
    e       = pk >> 16;
    rowTile = (pk & 0xffff) * 128;
    Mloc    = g_cnt[e];
    rowBase = g_off[e];
    return true;
}

__global__ void __launch_bounds__(256, 2) gemm_persist(
    const float* __restrict__ xf,
    const float* __restrict__ sb1, const float* __restrict__ db1,
    const float* __restrict__ sbg, const float* __restrict__ dbg,
    const float* __restrict__ sb2, const float* __restrict__ db2,
    float* __restrict__ out)
{
    extern __shared__ uint8_t sm[];
    __shared__ int s_task;
    uint32_t asb = smem_u32(sm);
    uint32_t bsb = asb + STAGES * BUFBY;

    int tid   = threadIdx.x;
    int lane  = tid & 31;
    int warp  = tid >> 5;
    int warpM = warp >> 2;
    int warpN = warp & 3;

    int srow = tid >> 3;
    int sseg = (tid & 7) * 8;
    int aoffB = (lane & 15) * ROWB + ((lane >> 4) << 4);
    int boffB = (lane & 7)  * ROWB + (((lane >> 3) & 1) << 4);
    int grp = lane >> 2, t4 = lane & 3;

    for (;;) {
        if (tid == 0) s_task = atomicAdd(&g_task, 1);
        __syncthreads();                  // all warps done with prior tile's smem
        int t = s_task;
        if (t >= TASK_TOTAL) return;

        // ---- decode ----
        int task, gy, bx;
        if (t < TASK_PROD) {
            gy = t / 40; int c = t - gy * 40;
            if (c < 32) { task = TASK_ACT;  bx = c; }
            else        { task = TASK_GATE; bx = c - 32; }
        } else {
            int u = t - TASK_PROD;
            task = TASK_MIX; gy = u >> 3; bx = u & 7;
        }

        bool dom = gy >= 64;
        int e = 0, Mloc = NTOK, rowBase = 0, rowTile = 0;
        if (!dom) rowTile = gy * 128;
        else if (!dom_tile(gy - 64, e, Mloc, rowBase, rowTile)) continue;

        const bf16 *A, *Wt;
        const float* bias;
        int K;
        if (task == TASK_ACT) {
            K = DIM;
            A    = dom ? g_Xgb + (size_t)rowBase * K : g_Xb;
            Wt   = dom ? g_dW1t + (size_t)e * (size_t)K * FFN : g_sW1t;
            bias = dom ? db1 + (size_t)e * FFN : sb1;
        } else if (task == TASK_GATE) {
            K = DIM;
            A    = dom ? g_Xgb + (size_t)rowBase * K : g_Xb;
            Wt   = dom ? g_dWgt + (size_t)e * (size_t)K * DIM : g_sWgt;
            bias = dom ? dbg + (size_t)e * DIM : sbg;
        } else {
            K = FFN;
            A    = (dom ? g_Ad : g_Ab) + (dom ? (size_t)rowBase * K : 0);
            Wt   = dom ? g_dW2t + (size_t)e * (size_t)K * DIM : g_sW2t;
            bias = dom ? db2 + (size_t)e * DIM : sb2;
            if (tid == 0) spin_ge(&g_rowCnt[gy], DEP_TARGET);
            __syncthreads();
            __threadfence();              // acquire
        }

        int colTile = bx * 128;

        float acc[4][4][4];
#pragma unroll
        for (int mi = 0; mi < 4; mi++)
#pragma unroll
            for (int ni = 0; ni < 4; ni++)
#pragma unroll
                for (int j = 0; j < 4; j++) acc[mi][ni][j] = 0.f;

        const int chunks = K >> 6;

#define ISSUE(chunk, slot)                                                        \
        do {                                                                      \
            int _kk = (chunk) << 6;                                               \
            uint32_t _aO = asb + (uint32_t)(slot) * BUFBY;                        \
            uint32_t _bO = bsb + (uint32_t)(slot) * BUFBY;                        \
            _Pragma("unroll")                                                     \
            for (int _p = 0; _p < 4; _p++) {                                      \
                int _row = srow + _p * 32;                                        \
                int _av  = (rowTile + _row) < Mloc ? 16 : 0;                      \
                cp16(_aO + (uint32_t)(_row * ROWB + sseg * 2),                    \
                     A + (size_t)(rowTile + _row) * K + _kk + sseg, _av);         \
                cp16(_bO + (uint32_t)(_row * ROWB + sseg * 2),                    \
                     Wt + (size_t)(colTile + _row) * K + _kk + sseg, 16);         \
            }                                                                     \
            cp_commit();                                                          \
        } while (0)

        ISSUE(0, 0);
        ISSUE(1, 1);

        int sCur = 0;
        for (int i = 0; i < chunks; i++) {
            if (i + 1 < chunks) cp_wait<1>();
            else                cp_wait<0>();
            __syncthreads();
            if (i + 2 < chunks) {
                int slot = sCur + 2; if (slot >= STAGES) slot -= STAGES;
                ISSUE(i + 2, slot);
            }
            uint32_t aBuf = asb + (uint32_t)sCur * BUFBY;
            uint32_t bBuf = bsb + (uint32_t)sCur * BUFBY;
#pragma unroll
            for (int kb = 0; kb < 64; kb += 16) {
                uint32_t af[4][4], bfr[4][2];
#pragma unroll
                for (int mi = 0; mi < 4; mi++)
                    ldsm_x4(af[mi], aBuf + (uint32_t)((warpM * 64 + mi * 16) * ROWB + kb * 2 + aoffB));
#pragma unroll
                for (int ni = 0; ni < 4; ni++)
                    ldsm_x2(bfr[ni], bBuf + (uint32_t)((warpN * 32 + ni * 8) * ROWB + kb * 2 + boffB));
#pragma unroll
                for (int mi = 0; mi < 4; mi++)
#pragma unroll
                    for (int ni = 0; ni < 4; ni++)
                        mma_bf16(acc[mi][ni], af[mi], bfr[ni]);
            }
            if (++sCur == STAGES) sCur = 0;
        }
#undef ISSUE

        // ---- epilogue ----
#pragma unroll
        for (int mi = 0; mi < 4; mi++)
#pragma unroll
            for (int h = 0; h < 2; h++) {
                int lr = rowTile + warpM * 64 + mi * 16 + grp + h * 8;
                if (lr >= Mloc) continue;
                int grow = dom ? rowBase + lr : lr;
#pragma unroll
                for (int ni = 0; ni < 4; ni++) {
                    int col = colTile + warpN * 32 + ni * 8 + t4 * 2;
                    float v0 = acc[mi][ni][h * 2 + 0];
                    float v1 = acc[mi][ni][h * 2 + 1];
                    if (task == TASK_ACT) {
                        float a0 = v0 + bias[col];
                        float a1 = v1 + bias[col + 1];
                        a0 = 0.5f * a0 * (1.0f + erff(a0 * 0.70710678118654752f));
                        a1 = 0.5f * a1 * (1.0f + erff(a1 * 0.70710678118654752f));
                        union { __nv_bfloat162 h2; uint32_t u; } cv;
                        cv.h2 = __floats2bfloat162_rn(a0, a1);
                        *(uint32_t*)((dom ? g_Ad : g_Ab) + (size_t)grow * FFN + col) = cv.u;
                    } else if (task == TASK_GATE) {
                        float* dst = (dom ? g_Gd : g_G) + (size_t)grow * DIM + col;
                        dst[0] = 1.0f / (1.0f + expf(-(v0 + bias[col])));
                        dst[1] = 1.0f / (1.0f + expf(-(v1 + bias[col + 1])));
                    } else {
                        const float* xp = (dom ? g_Xg : xf) + (size_t)grow * DIM + col;
                        const float* gp = (dom ? g_Gd : g_G) + (size_t)grow * DIM + col;
                        float x0 = xp[0], x1 = xp[1];
                        float h0 = v0 + bias[col]     + x0;
                        float h1 = v1 + bias[col + 1] + x1;
                        float g0 = gp[0], g1 = gp[1];
                        float o0 = g0 * h0 + (1.0f - g0) * x0;
                        float o1 = g1 * h1 + (1.0f - g1) * x1;
                        float* dst = (dom ? g_Od + (size_t)grow * DIM
                                          : out + (size_t)grow * DIM) + col;
                        dst[0] = o0;
                        dst[1] = o1;
                    }
                }
            }

        // ---- release signals ----
        if (task != TASK_MIX) {
            __threadfence();
            __syncthreads();
            if (tid == 0) atomicAdd(&g_rowCnt[gy], 1);
        }
    }
}

// ---------------- launch -----------------------------------------------------
extern "C" void kernel_launch(void* const* d_in, const int* in_sizes, int n_in,
                              void* d_out, int out_size)
{
    const float* x   = (const float*)d_in[0];
    const int*   ids = (const int*)  d_in[1];
    const float* sW1 = (const float*)d_in[2];
    const float* sb1 = (const float*)d_in[3];
    const float* sW2 = (const float*)d_in[4];
    const float* sb2 = (const float*)d_in[5];
    const float* sWg = (const float*)d_in[6];
    const float* sbg = (const float*)d_in[7];
    const float* dW1 = (const float*)d_in[8];
    const float* db1 = (const float*)d_in[9];
    const float* dW2 = (const float*)d_in[10];
    const float* db2 = (const float*)d_in[11];
    const float* dWg = (const float*)d_in[12];
    const float* dbg = (const float*)d_in[13];
    float* out = (float*)d_out;

    cudaFuncSetAttribute(gemm_persist, cudaFuncAttributeMaxDynamicSharedMemorySize, SMEM_BYTES);

    // zero counters, then merged prep (x convert + count | weight transposes)
    k_zero<<<1, 256>>>();
    k_prep<<<PREP_BLOCKS, dim3(32, 8)>>>(ids, x, sW1, sW2, sWg, dW1, dW2, dWg);
    k_scan_scatter<<<1, 256>>>(ids);
    k_gather<<<NTOK, 256>>>(x);

    // ONE persistent launch: ACT + GATE + MIX via task queue (R12 structure)
    gemm_persist<<<304, 256, SMEM_BYTES>>>(x, sb1, db1, sbg, dbg, sb2, db2, out);

    // Combine: out[perm[p]] += domain mix
    k_combine<<<NTOK, 256>>>(out);
}